// round 1
// baseline (speedup 1.0000x reference)
#include <cuda_runtime.h>

// SNN forward scan: B=64, N=1024, T=512.
// One thread per (b,n) row; serial recurrence along T in registers.
// x: [B,N,T] fp32 row-contiguous per thread -> float4 loads, unroll for MLP.

#define T_STEPS 512
#define T_LAT 2.0f

__global__ __launch_bounds__(256) void snn_fwd_kernel(
    const float* __restrict__ x,
    const float* __restrict__ beta,
    const float* __restrict__ p,
    const float* __restrict__ b,
    float* __restrict__ out,
    int N)
{
    const int row = blockIdx.x * blockDim.x + threadIdx.x;
    const int n = row % N;

    // clamped effective params (per-neuron)
    const float beta_c = fminf(fmaxf(beta[n], 0.001f), 0.999f);
    const float p_c    = fminf(fabsf(p[n]), 0.999f);
    const float b_c    = fminf(fmaxf(fabsf(b[n]), 0.001f), 1.0f);

    const float4* __restrict__ xr =
        reinterpret_cast<const float4*>(x + (size_t)row * T_STEPS);
    float4* __restrict__ orow =
        reinterpret_cast<float4*>(out + (size_t)row * T_STEPS);

    // state
    float mem = 0.0f, s = 0.0f, refac = T_LAT, a = 0.0f, vth = 1.0f;

    #pragma unroll 4
    for (int i = 0; i < T_STEPS / 4; ++i) {
        float4 xv = xr[i];
        float4 ov;

        #pragma unroll
        for (int k = 0; k < 4; ++k) {
            const float xt = (k == 0) ? xv.x : (k == 1) ? xv.y : (k == 2) ? xv.z : xv.w;
            // spike-triggered refractory reset, mask input during window
            refac = (s > 0.0f) ? 0.0f : refac;
            const float ic = (refac < T_LAT) ? 0.0f : xt;
            refac += 1.0f;
            // leaky integration
            const float nm = fmaf(mem, beta_c, ic);
            // spike
            s = (nm - vth > 0.0f) ? 1.0f : 0.0f;
            // reset-to-zero on spike
            mem = (s > 0.0f) ? 0.0f : nm;
            // adaptive threshold
            a = fmaf(p_c, a, s);
            vth = fmaf(b_c, a, 1.0f);

            if (k == 0) ov.x = s; else if (k == 1) ov.y = s;
            else if (k == 2) ov.z = s; else ov.w = s;
        }
        orow[i] = ov;
    }
}

extern "C" void kernel_launch(void* const* d_in, const int* in_sizes, int n_in,
                              void* d_out, int out_size)
{
    const float* x    = (const float*)d_in[0];
    const float* beta = (const float*)d_in[1];
    const float* p    = (const float*)d_in[2];
    const float* b    = (const float*)d_in[3];
    float* out        = (float*)d_out;

    const int N = in_sizes[1];                 // 1024
    const int rows = in_sizes[0] / T_STEPS;    // B*N = 65536

    const int threads = 256;
    const int blocks = (rows + threads - 1) / threads;
    snn_fwd_kernel<<<blocks, threads>>>(x, beta, p, b, out, N);
}

// round 2
// speedup vs baseline: 1.4758x; 1.4758x over previous
#include <cuda_runtime.h>

// SNN forward scan, smem-staged version.
// x:[B*N, T] fp32. One thread per row; global traffic staged through shared
// memory in 32-step chunks so every 128B line is fully consumed (coalesced),
// eliminating the 32-wavefronts-per-warp-load pattern of the direct version.

#define T_STEPS 512
#define CHUNK   32
#define ROWS    128              // rows per block == threads per block
#define NCHUNK  (T_STEPS / CHUNK) // 16
#define STRIDE  36               // padded floats per smem row (16B-aligned, conflict-free)
#define T_LAT   2.0f

__device__ __forceinline__ void cp_async16(float* smem_dst, const float* gmem_src) {
    unsigned saddr = (unsigned)__cvta_generic_to_shared(smem_dst);
    asm volatile("cp.async.cg.shared.global [%0], [%1], 16;\n"
                 :: "r"(saddr), "l"(gmem_src));
}

__global__ __launch_bounds__(ROWS) void snn_fwd_kernel(
    const float* __restrict__ x,
    const float* __restrict__ beta,
    const float* __restrict__ p,
    const float* __restrict__ b,
    float* __restrict__ out,
    int N)
{
    __shared__ float tile[2][ROWS * STRIDE];

    const int tid = threadIdx.x;
    const size_t row_base = (size_t)blockIdx.x * ROWS;
    const int n = (int)((row_base + tid) % (size_t)N);

    // clamped effective per-neuron params
    const float beta_c = fminf(fmaxf(beta[n], 0.001f), 0.999f);
    const float p_c    = fminf(fabsf(p[n]), 0.999f);
    const float b_c    = fminf(fmaxf(fabsf(b[n]), 0.001f), 1.0f);

    // state (registers, persistent across chunks)
    float mem = 0.0f, s = 0.0f, refac = T_LAT, a = 0.0f, vth = 1.0f;

    // cooperative-load addressing: g in [0,1024): r = g>>3 (row), c4 = g&7 (16B slot)
    // 8 consecutive threads cover one row-chunk's 128B -> fully coalesced.

    // preload chunk 0 into buffer 0
    #pragma unroll
    for (int k = 0; k < 8; ++k) {
        const int g = k * ROWS + tid;
        const int r = g >> 3, c4 = g & 7;
        cp_async16(&tile[0][r * STRIDE + c4 * 4],
                   x + (row_base + r) * T_STEPS + c4 * 4);
    }
    asm volatile("cp.async.commit_group;\n");

    for (int c = 0; c < NCHUNK; ++c) {
        const int buf = c & 1;

        if (c + 1 < NCHUNK) {
            // issue next chunk into the other buffer (its store finished last iter)
            #pragma unroll
            for (int k = 0; k < 8; ++k) {
                const int g = k * ROWS + tid;
                const int r = g >> 3, c4 = g & 7;
                cp_async16(&tile[buf ^ 1][r * STRIDE + c4 * 4],
                           x + (row_base + r) * T_STEPS + (c + 1) * CHUNK + c4 * 4);
            }
            asm volatile("cp.async.commit_group;\n");
            asm volatile("cp.async.wait_group 1;\n");
        } else {
            asm volatile("cp.async.wait_group 0;\n");
        }
        __syncthreads();

        // compute: each thread owns one smem row; read x, write spikes in place
        float* rowp = &tile[buf][tid * STRIDE];
        #pragma unroll
        for (int i = 0; i < CHUNK / 4; ++i) {
            float4 xv = *reinterpret_cast<float4*>(rowp + i * 4);
            float4 ov;
            #pragma unroll
            for (int k = 0; k < 4; ++k) {
                const float xt = (k == 0) ? xv.x : (k == 1) ? xv.y
                               : (k == 2) ? xv.z : xv.w;
                refac = (s > 0.0f) ? 0.0f : refac;
                const float ic = (refac < T_LAT) ? 0.0f : xt;
                refac += 1.0f;
                const float nm = fmaf(mem, beta_c, ic);
                s = (nm - vth > 0.0f) ? 1.0f : 0.0f;
                mem = (s > 0.0f) ? 0.0f : nm;
                a = fmaf(p_c, a, s);
                vth = fmaf(b_c, a, 1.0f);
                if (k == 0) ov.x = s; else if (k == 1) ov.y = s;
                else if (k == 2) ov.z = s; else ov.w = s;
            }
            *reinterpret_cast<float4*>(rowp + i * 4) = ov;
        }
        __syncthreads();

        // cooperative coalesced store of spikes
        #pragma unroll
        for (int k = 0; k < 8; ++k) {
            const int g = k * ROWS + tid;
            const int r = g >> 3, c4 = g & 7;
            const float4 v = *reinterpret_cast<const float4*>(
                &tile[buf][r * STRIDE + c4 * 4]);
            *reinterpret_cast<float4*>(
                out + (row_base + r) * T_STEPS + c * CHUNK + c4 * 4) = v;
        }
        __syncthreads();  // buffer reusable for load of chunk c+2
    }
}

extern "C" void kernel_launch(void* const* d_in, const int* in_sizes, int n_in,
                              void* d_out, int out_size)
{
    const float* x    = (const float*)d_in[0];
    const float* beta = (const float*)d_in[1];
    const float* p    = (const float*)d_in[2];
    const float* b    = (const float*)d_in[3];
    float* out        = (float*)d_out;

    const int N    = in_sizes[1];               // 1024
    const int rows = in_sizes[0] / T_STEPS;     // B*N = 65536

    const int blocks = rows / ROWS;             // 512
    snn_fwd_kernel<<<blocks, ROWS>>>(x, beta, p, b, out, N);
}

// round 3
// speedup vs baseline: 1.4823x; 1.0044x over previous
#include <cuda_runtime.h>

// SNN forward scan: rows = B*N = 65536 independent length-512 recurrences.
// Smem-staged, 3-buffer / depth-2 cp.async pipeline, coalesced 128B gmem
// traffic both directions. Refractory window rewritten as multiplicative
// mask: ic(t) = x(t) * (1-s(t-1)) * (1-s(t-2))  (exactly the refac<2 logic,
// since mem is reset to 0 on spike so no spikes occur inside the window).

#define T_STEPS 512
#define CHUNK   32
#define ROWS    128               // threads per block == rows per block
#define NCHUNK  (T_STEPS / CHUNK) // 16
#define STRIDE  36                // padded smem row stride (floats)
#define NBUF    3

__device__ __forceinline__ void cp_async16(float* smem_dst, const float* gmem_src) {
    unsigned saddr = (unsigned)__cvta_generic_to_shared(smem_dst);
    asm volatile("cp.async.cg.shared.global [%0], [%1], 16;\n"
                 :: "r"(saddr), "l"(gmem_src));
}

__global__ __launch_bounds__(ROWS) void snn_fwd_kernel(
    const float* __restrict__ x,
    const float* __restrict__ beta,
    const float* __restrict__ p,
    const float* __restrict__ b,
    float* __restrict__ out,
    int N)
{
    __shared__ float tile[NBUF][ROWS * STRIDE];

    const int tid = threadIdx.x;
    const size_t row_base = (size_t)blockIdx.x * ROWS;
    const int n = (int)((row_base + tid) % (size_t)N);

    // clamped effective per-neuron params
    const float beta_c = fminf(fmaxf(beta[n], 0.001f), 0.999f);
    const float p_c    = fminf(fabsf(p[n]), 0.999f);
    const float b_c    = fminf(fmaxf(fabsf(b[n]), 0.001f), 1.0f);

    // recurrence state
    float mem = 0.0f, a = 0.0f, vth = 1.0f;
    float m1 = 1.0f, m2 = 1.0f;   // 1 - s(t-1), 1 - s(t-2)

    // cooperative addressing: g = k*ROWS + tid; r = g>>3 row, c4 = g&7 16B slot.
    // 8 consecutive threads cover one row-chunk's 128 B -> fully coalesced.

    // preload chunks 0 and 1 (one commit group each)
    #pragma unroll
    for (int cc = 0; cc < 2; ++cc) {
        #pragma unroll
        for (int k = 0; k < 8; ++k) {
            const int g = k * ROWS + tid;
            const int r = g >> 3, c4 = g & 7;
            cp_async16(&tile[cc][r * STRIDE + c4 * 4],
                       x + (row_base + r) * T_STEPS + cc * CHUNK + c4 * 4);
        }
        asm volatile("cp.async.commit_group;\n");
    }

    for (int c = 0; c < NCHUNK; ++c) {
        const int buf = c % NBUF;

        if (c + 1 < NCHUNK) asm volatile("cp.async.wait_group 1;\n");
        else                asm volatile("cp.async.wait_group 0;\n");
        __syncthreads();   // chunk c visible; also: everyone done reading buf (c+2)%NBUF

        // prefetch chunk c+2 immediately (keeps >=2 loads in flight)
        if (c + 2 < NCHUNK) {
            const int buf2 = (c + 2) % NBUF;
            #pragma unroll
            for (int k = 0; k < 8; ++k) {
                const int g = k * ROWS + tid;
                const int r = g >> 3, c4 = g & 7;
                cp_async16(&tile[buf2][r * STRIDE + c4 * 4],
                           x + (row_base + r) * T_STEPS + (c + 2) * CHUNK + c4 * 4);
            }
            asm volatile("cp.async.commit_group;\n");
        }

        // compute: each thread owns one smem row; overwrite x with spikes
        float* rowp = &tile[buf][tid * STRIDE];
        #pragma unroll
        for (int i = 0; i < CHUNK / 4; ++i) {
            float4 xv = *reinterpret_cast<float4*>(rowp + i * 4);
            float4 ov;
            #pragma unroll
            for (int k = 0; k < 4; ++k) {
                const float xt = (k == 0) ? xv.x : (k == 1) ? xv.y
                               : (k == 2) ? xv.z : xv.w;
                const float ic = xt * (m1 * m2);          // refractory mask
                const float nm = fmaf(mem, beta_c, ic);   // leaky integrate
                const bool  sp = nm > vth;
                const float s  = sp ? 1.0f : 0.0f;
                const float ns = sp ? 0.0f : 1.0f;
                mem = nm * ns;                            // reset-to-zero
                a   = fmaf(p_c, a, s);                    // adaptation
                vth = fmaf(b_c, a, 1.0f);
                m2 = m1; m1 = ns;
                if (k == 0) ov.x = s; else if (k == 1) ov.y = s;
                else if (k == 2) ov.z = s; else ov.w = s;
            }
            *reinterpret_cast<float4*>(rowp + i * 4) = ov;
        }
        __syncthreads();   // spikes visible for cooperative store

        // cooperative coalesced streaming store
        #pragma unroll
        for (int k = 0; k < 8; ++k) {
            const int g = k * ROWS + tid;
            const int r = g >> 3, c4 = g & 7;
            const float4 v = *reinterpret_cast<const float4*>(
                &tile[buf][r * STRIDE + c4 * 4]);
            __stcs(reinterpret_cast<float4*>(
                out + (row_base + r) * T_STEPS + c * CHUNK + c4 * 4), v);
        }
        // no trailing barrier: reuse of this buffer is gated by the
        // wait_group + __syncthreads at the top of iteration c+1.
    }
}

extern "C" void kernel_launch(void* const* d_in, const int* in_sizes, int n_in,
                              void* d_out, int out_size)
{
    const float* x    = (const float*)d_in[0];
    const float* beta = (const float*)d_in[1];
    const float* p    = (const float*)d_in[2];
    const float* b    = (const float*)d_in[3];
    float* out        = (float*)d_out;

    const int N    = in_sizes[1];               // 1024
    const int rows = in_sizes[0] / T_STEPS;     // B*N = 65536

    const int blocks = rows / ROWS;             // 512
    snn_fwd_kernel<<<blocks, ROWS>>>(x, beta, p, b, out, N);
}

// round 4
// speedup vs baseline: 1.5962x; 1.0768x over previous
#include <cuda_runtime.h>

// SNN forward scan: rows = B*N = 65536 independent length-512 recurrences.
// 64 rows per 64-thread block -> grid 1024 (near-perfect SM balance vs 512).
// Smem-staged, 3-buffer depth-2 cp.async pipeline, fully coalesced 128B
// global traffic both ways. Refractory window as multiplicative mask:
// ic(t) = x(t) * (1-s(t-1)) * (1-s(t-2)).

#define T_STEPS 512
#define CHUNK   32
#define ROWS    64                // threads per block == rows per block
#define NCHUNK  (T_STEPS / CHUNK) // 16
#define STRIDE  36                // padded smem row stride (floats)
#define NBUF    3

__device__ __forceinline__ void cp_async16(float* smem_dst, const float* gmem_src) {
    unsigned saddr = (unsigned)__cvta_generic_to_shared(smem_dst);
    asm volatile("cp.async.cg.shared.global [%0], [%1], 16;\n"
                 :: "r"(saddr), "l"(gmem_src));
}

__global__ __launch_bounds__(ROWS) void snn_fwd_kernel(
    const float* __restrict__ x,
    const float* __restrict__ beta,
    const float* __restrict__ p,
    const float* __restrict__ b,
    float* __restrict__ out,
    int N)
{
    __shared__ float tile[NBUF][ROWS * STRIDE];

    const int tid = threadIdx.x;
    const size_t row_base = (size_t)blockIdx.x * ROWS;
    const int n = (int)((row_base + tid) % (size_t)N);

    // clamped effective per-neuron params
    const float beta_c = fminf(fmaxf(beta[n], 0.001f), 0.999f);
    const float p_c    = fminf(fabsf(p[n]), 0.999f);
    const float b_c    = fminf(fmaxf(fabsf(b[n]), 0.001f), 1.0f);

    // recurrence state
    float mem = 0.0f, a = 0.0f, vth = 1.0f;
    float m1 = 1.0f, m2 = 1.0f;   // 1 - s(t-1), 1 - s(t-2)

    // cooperative addressing: g = k*ROWS + tid, g in [0, 512):
    // r = g>>3 (row), c4 = g&7 (16B slot); 8 consecutive threads cover
    // one row-chunk's 128 B -> fully coalesced lines.

    // preload chunks 0 and 1
    #pragma unroll
    for (int cc = 0; cc < 2; ++cc) {
        #pragma unroll
        for (int k = 0; k < 8; ++k) {
            const int g = k * ROWS + tid;
            const int r = g >> 3, c4 = g & 7;
            cp_async16(&tile[cc][r * STRIDE + c4 * 4],
                       x + (row_base + r) * T_STEPS + cc * CHUNK + c4 * 4);
        }
        asm volatile("cp.async.commit_group;\n");
    }

    for (int c = 0; c < NCHUNK; ++c) {
        const int buf = c % NBUF;

        if (c + 1 < NCHUNK) asm volatile("cp.async.wait_group 1;\n");
        else                asm volatile("cp.async.wait_group 0;\n");
        __syncthreads();   // chunk c visible; buffer (c+2)%NBUF free

        // prefetch chunk c+2
        if (c + 2 < NCHUNK) {
            const int buf2 = (c + 2) % NBUF;
            #pragma unroll
            for (int k = 0; k < 8; ++k) {
                const int g = k * ROWS + tid;
                const int r = g >> 3, c4 = g & 7;
                cp_async16(&tile[buf2][r * STRIDE + c4 * 4],
                           x + (row_base + r) * T_STEPS + (c + 2) * CHUNK + c4 * 4);
            }
            asm volatile("cp.async.commit_group;\n");
        }

        // compute: each thread owns one smem row; overwrite x with spikes
        float* rowp = &tile[buf][tid * STRIDE];
        #pragma unroll
        for (int i = 0; i < CHUNK / 4; ++i) {
            float4 xv = *reinterpret_cast<float4*>(rowp + i * 4);
            float4 ov;
            #pragma unroll
            for (int k = 0; k < 4; ++k) {
                const float xt = (k == 0) ? xv.x : (k == 1) ? xv.y
                               : (k == 2) ? xv.z : xv.w;
                const float ic = xt * (m1 * m2);          // refractory mask
                const float nm = fmaf(mem, beta_c, ic);   // leaky integrate
                const float ns = (nm > vth) ? 0.0f : 1.0f;
                const float s  = 1.0f - ns;
                mem = nm * ns;                            // reset-to-zero
                a   = fmaf(p_c, a, s);                    // adaptation
                vth = fmaf(b_c, a, 1.0f);
                m2 = m1; m1 = ns;
                if (k == 0) ov.x = s; else if (k == 1) ov.y = s;
                else if (k == 2) ov.z = s; else ov.w = s;
            }
            *reinterpret_cast<float4*>(rowp + i * 4) = ov;
        }
        __syncthreads();   // spikes visible for cooperative store

        // cooperative coalesced streaming store
        #pragma unroll
        for (int k = 0; k < 8; ++k) {
            const int g = k * ROWS + tid;
            const int r = g >> 3, c4 = g & 7;
            const float4 v = *reinterpret_cast<const float4*>(
                &tile[buf][r * STRIDE + c4 * 4]);
            __stcs(reinterpret_cast<float4*>(
                out + (row_base + r) * T_STEPS + c * CHUNK + c4 * 4), v);
        }
        // buffer reuse gated by wait_group + __syncthreads at top of c+1
    }
}

extern "C" void kernel_launch(void* const* d_in, const int* in_sizes, int n_in,
                              void* d_out, int out_size)
{
    const float* x    = (const float*)d_in[0];
    const float* beta = (const float*)d_in[1];
    const float* p    = (const float*)d_in[2];
    const float* b    = (const float*)d_in[3];
    float* out        = (float*)d_out;

    const int N    = in_sizes[1];               // 1024
    const int rows = in_sizes[0] / T_STEPS;     // B*N = 65536

    const int blocks = rows / ROWS;             // 1024
    snn_fwd_kernel<<<blocks, ROWS>>>(x, beta, p, b, out, N);
}